// round 13
// baseline (speedup 1.0000x reference)
#include <cuda_runtime.h>
#include <cuda_bf16.h>
#include <cstdint>

// ---------------- problem constants ----------------
// T=4, B=2, Ck=256, Cv=512, H=W=96, scales {1,2,3,6}, MAX=6, M=144, N=9216

// ---------------- device scratch (static, no allocation) ----------------
__device__ __align__(16) float g_pool6_k[2048 * 36];
__device__ __align__(16) float g_pool6_v[4096 * 36];
__device__ __align__(16) float g_convk[4 * 2 * 4 * 64 * 36];
__device__ __align__(16) float g_convv[4 * 2 * 4 * 128 * 36];
__device__ __align__(16) __nv_bfloat16 g_mkh[2 * 144 * 256];  // [b][m][c] hi (x Ck^-0.5)
__device__ __align__(16) __nv_bfloat16 g_mkl[2 * 144 * 256];  // lo
__device__ __align__(16) __nv_bfloat16 g_mvh[2 * 512 * 144];  // [b][v][m] hi
__device__ __align__(16) __nv_bfloat16 g_mvl[2 * 512 * 144];  // lo

__constant__ int c_scale[4] = {1, 2, 3, 6};
__constant__ int UI0[4][6] = {
    {0,0,0,0,0,0},
    {0,0,0,0,1,1},
    {0,0,0,1,1,2},
    {0,1,2,3,4,5}};
__constant__ int UI1[4][6] = {
    {0,0,0,0,0,0},
    {0,1,1,1,1,1},
    {0,1,1,2,2,2},
    {0,1,2,3,4,5}};
__constant__ float UW[4][6] = {
    {0.f,0.f,0.f,0.f,0.f,0.f},
    {0.f, 1.f/6.f, 0.5f, 5.f/6.f, 0.f, 0.f},
    {0.f, 0.25f, 0.75f, 0.25f, 0.75f, 0.f},
    {0.f,0.f,0.f,0.f,0.f,0.f}};

// ---------------- asm helpers ----------------
__device__ __forceinline__ void mma_bf16(float* d, const unsigned* a, const unsigned* b) {
    asm volatile(
        "mma.sync.aligned.m16n8k16.row.col.f32.bf16.bf16.f32 "
        "{%0,%1,%2,%3}, {%4,%5,%6,%7}, {%8,%9}, {%0,%1,%2,%3};"
        : "+f"(d[0]), "+f"(d[1]), "+f"(d[2]), "+f"(d[3])
        : "r"(a[0]), "r"(a[1]), "r"(a[2]), "r"(a[3]), "r"(b[0]), "r"(b[1]));
}
__device__ __forceinline__ void ldsm4(unsigned* r, uint32_t a) {
    asm volatile("ldmatrix.sync.aligned.m8n8.x4.shared.b16 {%0,%1,%2,%3}, [%4];"
                 : "=r"(r[0]), "=r"(r[1]), "=r"(r[2]), "=r"(r[3]) : "r"(a));
}
__device__ __forceinline__ void ldsm2(unsigned* r, uint32_t a) {
    asm volatile("ldmatrix.sync.aligned.m8n8.x2.shared.b16 {%0,%1}, [%2];"
                 : "=r"(r[0]), "=r"(r[1]) : "r"(a));
}
__device__ __forceinline__ void cp16(uint32_t dst, const void* src) {
    asm volatile("cp.async.cg.shared.global [%0], [%1], 16;" :: "r"(dst), "l"(src));
}
__device__ __forceinline__ void cp_commit() { asm volatile("cp.async.commit_group;"); }
__device__ __forceinline__ void cp_wait1() { asm volatile("cp.async.wait_group 1;"); }
__device__ __forceinline__ void cp_wait0() { asm volatile("cp.async.wait_group 0;"); }

__device__ __forceinline__ void split_bf16(float x, __nv_bfloat16& hi, __nv_bfloat16& lo) {
    hi = __float2bfloat16(x);
    lo = __float2bfloat16(x - __bfloat162float(hi));
}
__device__ __forceinline__ unsigned packbf(__nv_bfloat16 l, __nv_bfloat16 h) {
    return ((unsigned)__bfloat16_as_ushort(h) << 16) | (unsigned)__bfloat16_as_ushort(l);
}

// ================= K1: 16x16 block means =================
__global__ void k_pool(const float* __restrict__ mk, const float* __restrict__ mv) {
    int p = blockIdx.x;
    int tid = threadIdx.x;
    const float* src; float* dst;
    if (p < 2048) { src = mk + (size_t)p * 9216; dst = g_pool6_k + (size_t)p * 36; }
    else { int q = p - 2048; src = mv + (size_t)q * 9216; dst = g_pool6_v + (size_t)q * 36; }
    __shared__ float rowsum[576];
    for (int task = tid; task < 576; task += 256) {
        int r = task / 6, j = task % 6;
        const float4* a = (const float4*)(src + r * 96 + j * 16);
        float4 v0 = a[0], v1 = a[1], v2 = a[2], v3 = a[3];
        rowsum[task] = (v0.x+v0.y+v0.z+v0.w) + (v1.x+v1.y+v1.z+v1.w)
                     + (v2.x+v2.y+v2.z+v2.w) + (v3.x+v3.y+v3.z+v3.w);
    }
    __syncthreads();
    if (tid < 36) {
        int by = tid / 6, bx = tid % 6;
        float s = 0.f;
        #pragma unroll
        for (int k = 0; k < 16; k++) s += rowsum[(by * 16 + k) * 6 + bx];
        dst[tid] = s * (1.0f / 256.0f);
    }
}

// ================= K2: per-(t,b,scale,pos) 1x1 conv + bias + relu =================
__global__ void k_conv(const float* __restrict__ kw, const float* __restrict__ kb,
                       const float* __restrict__ vw, const float* __restrict__ vb) {
    __shared__ float pooled[512];
    int bi = blockIdx.x;
    int kv = bi / 400;
    int rem = bi % 400;
    int tb = rem / 50;
    int task = rem % 50;
    int si, pos;
    if (task < 1)       { si = 0; pos = 0; }
    else if (task < 5)  { si = 1; pos = task - 1; }
    else if (task < 14) { si = 2; pos = task - 5; }
    else                { si = 3; pos = task - 14; }
    int s = c_scale[si];
    int g = 6 / s;
    int pi = pos / s, pj = pos % s;
    int C  = kv ? 512 : 256;
    int Co = kv ? 128 : 64;
    const float* p6 = kv ? g_pool6_v : g_pool6_k;
    int tid = threadIdx.x;
    float ginv = 1.0f / (float)(g * g);
    for (int c = tid; c < C; c += 256) {
        const float* pp = p6 + (size_t)(tb * C + c) * 36;
        float sum = 0.f;
        for (int a = 0; a < g; a++)
            for (int bb = 0; bb < g; bb++)
                sum += pp[(pi * g + a) * 6 + (pj * g + bb)];
        pooled[c] = sum * ginv;
    }
    __syncthreads();
    int t = tb >> 1;
    int L = 256 / Co;
    int o = tid / L, r = tid % L;
    int chunk = C / L;
    const float* w = (kv ? vw : kw) + (size_t)((t * 4 + si) * Co + o) * C + r * chunk;
    const float* pl = pooled + r * chunk;
    float partial = 0.f;
    for (int i = 0; i < chunk; i += 4) {
        float4 wv = *(const float4*)(w + i);
        float4 pv = *(const float4*)(pl + i);
        partial += wv.x * pv.x + wv.y * pv.y + wv.z * pv.z + wv.w * pv.w;
    }
    for (int off = 1; off < L; off <<= 1)
        partial += __shfl_xor_sync(0xffffffffu, partial, off);
    if (r == 0) {
        float bias = (kv ? vb : kb)[(t * 4 + si) * Co + o];
        float v = fmaxf(partial + bias, 0.0f);
        float* cdst = (kv ? g_convv : g_convk) + (size_t)((tb * 4 + si) * Co + o) * 36 + pos;
        *cdst = v;
    }
}

// ================= K3: bilinear upsample + bf16 hi/lo layouts =================
__global__ void k_upsample() {
    int idx = blockIdx.x * 256 + threadIdx.x;
    if (idx >= 221184) return;
    if (idx < 73728) {
        int b = idx / (256 * 144);
        int rr = idx % (256 * 144);
        int c = rr / 144, m = rr % 144;
        int t = m / 36, pp = m % 36, i6 = pp / 6, j6 = pp % 6;
        int si = c >> 6, o = c & 63;
        int s = c_scale[si];
        const float* cv = g_convk + (size_t)(((t * 2 + b) * 4 + si) * 64 + o) * 36;
        int yi0 = UI0[si][i6], yi1 = UI1[si][i6]; float wy = UW[si][i6];
        int xi0 = UI0[si][j6], xi1 = UI1[si][j6]; float wx = UW[si][j6];
        float v00 = cv[yi0 * s + xi0], v01 = cv[yi0 * s + xi1];
        float v10 = cv[yi1 * s + xi0], v11 = cv[yi1 * s + xi1];
        float v = (1.f - wy) * ((1.f - wx) * v00 + wx * v01)
                +        wy  * ((1.f - wx) * v10 + wx * v11);
        v *= 0.0625f;
        __nv_bfloat16 hi, lo;
        split_bf16(v, hi, lo);
        size_t di = (size_t)(b * 144 + m) * 256 + c;
        g_mkh[di] = hi; g_mkl[di] = lo;
    } else {
        int r0 = idx - 73728;
        int b = r0 / (144 * 512);
        int rr = r0 % (144 * 512);
        int m = rr / 512, vch = rr % 512;
        int t = m / 36, pp = m % 36, i6 = pp / 6, j6 = pp % 6;
        int si = vch >> 7, o = vch & 127;
        int s = c_scale[si];
        const float* cv = g_convv + (size_t)(((t * 2 + b) * 4 + si) * 128 + o) * 36;
        int yi0 = UI0[si][i6], yi1 = UI1[si][i6]; float wy = UW[si][i6];
        int xi0 = UI0[si][j6], xi1 = UI1[si][j6]; float wx = UW[si][j6];
        float v00 = cv[yi0 * s + xi0], v01 = cv[yi0 * s + xi1];
        float v10 = cv[yi1 * s + xi0], v11 = cv[yi1 * s + xi1];
        float v = (1.f - wy) * ((1.f - wx) * v00 + wx * v01)
                +        wy  * ((1.f - wx) * v10 + wx * v11);
        __nv_bfloat16 hi, lo;
        split_bf16(v, hi, lo);
        size_t di = (size_t)(b * 512 + vch) * 144 + m;
        g_mvh[di] = hi; g_mvl[di] = lo;
    }
}

// ================= K4: tensor-core attention, cp.async double-buffered, ldmatrix =================
// grid 144 = 2 b x 72 n-tiles of 128; 512 threads = 16 warps.
//
// smem byte map (dynamic, total 126976):
//  QK phase : mkbuf0 @0      (hi 11520 + lo 11520 = 23040)   [144m][40c] pitch 40
//             mkbuf1 @23040
//             qkbuf0 @46080  (hi 10240 + lo 10240 = 20480)   [128n][40c] pitch 40
//             qkbuf1 @66560                                   (ends 87040)
//  AV phase : attT_hi @0     [128n][152m] 38912
//             attT_lo @38912                                  (ends 77824)
//             mvbuf0 @77824  (hi 12288 + lo 12288 = 24576)   [256v][24k] pitch 24
//             mvbuf1 @102400                                  (ends 126976)
__global__ __launch_bounds__(512, 1)
void k_attn(const float* __restrict__ qk, const float* __restrict__ qv,
            float* __restrict__ out) {
    extern __shared__ char smem[];
    uint32_t sbase = (uint32_t)__cvta_generic_to_shared(smem);
    __nv_bfloat16* attT_hi = (__nv_bfloat16*)(smem);
    __nv_bfloat16* attT_lo = (__nv_bfloat16*)(smem + 38912);

    int tid = threadIdx.x;
    int w = tid >> 5, lane = tid & 31;
    int g = lane >> 2, tq = lane & 3;
    int lane15 = lane & 15, lanehalf = (lane >> 4) & 1;
    int lane7 = lane & 7, laneb = (lane >> 3) & 1;
    int b = blockIdx.x / 72, ntile = blockIdx.x % 72;
    int n0 = ntile * 128;

    const float* qkb = qk + (size_t)b * 256 * 9216 + n0;
    const float* qvb = qv + (size_t)(b * 512) * 9216 + n0;
    float* outb = out + (size_t)(b * 1024) * 9216 + n0;

    // ---------------- phase 1: QK scores ----------------
    float acc[9][4];
    #pragma unroll
    for (int i = 0; i < 9; i++)
        #pragma unroll
        for (int j = 0; j < 4; j++) acc[i][j] = 0.f;

    // qk register prefetch mapping: thread owns column n, c-pairs {cb, cb+1} at i*8 strides
    int qn = tid & 127;
    int cb = (tid >> 7) * 2;
    float qcur[8], qnext[8];

    // prologue: stage mk(0), prefetch qk(0)
    {
        #pragma unroll
        for (int q = tid; q < 1152; q += 512) {
            int hl = q / 576, rem = q % 576;
            int m = rem % 144, part = rem / 144;
            const __nv_bfloat16* src = (hl ? g_mkl : g_mkh)
                                     + ((size_t)(b * 144 + m)) * 256 + part * 8;
            cp16(sbase + hl * 11520 + (m * 40 + part * 8) * 2, src);
        }
        cp_commit();
        #pragma unroll
        for (int i = 0; i < 4; i++) {
            int row = cb + i * 8;
            qcur[2*i]   = qkb[(size_t)row * 9216 + qn];
            qcur[2*i+1] = qkb[(size_t)(row + 1) * 9216 + qn];
        }
    }

    for (int cc = 0; cc < 8; cc++) {
        int cur = cc & 1;
        uint32_t mkb = sbase + cur * 23040;
        uint32_t qkbuf = sbase + 46080 + cur * 20480;
        // stage mk(cc+1)
        if (cc < 7) {
            uint32_t mkn = sbase + (1 - cur) * 23040;
            #pragma unroll
            for (int q = tid; q < 1152; q += 512) {
                int hl = q / 576, rem = q % 576;
                int m = rem % 144, part = rem / 144;
                const __nv_bfloat16* src = (hl ? g_mkl : g_mkh)
                                         + ((size_t)(b * 144 + m)) * 256 + (cc + 1) * 32 + part * 8;
                cp16(mkn + hl * 11520 + (m * 40 + part * 8) * 2, src);
            }
            cp_commit();
        }
        // split-store current qk chunk into qkbuf[cur]
        #pragma unroll
        for (int i = 0; i < 4; i++) {
            int c0 = cb + i * 8;
            __nv_bfloat16 h0, l0, h1, l1;
            split_bf16(qcur[2*i], h0, l0);
            split_bf16(qcur[2*i+1], h1, l1);
            *(unsigned*)(smem + (qkbuf - sbase) + (qn * 40 + c0) * 2)         = packbf(h0, h1);
            *(unsigned*)(smem + (qkbuf - sbase) + 10240 + (qn * 40 + c0) * 2) = packbf(l0, l1);
        }
        // prefetch qk(cc+1)
        if (cc < 7) {
            #pragma unroll
            for (int i = 0; i < 4; i++) {
                int row = (cc + 1) * 32 + cb + i * 8;
                qnext[2*i]   = qkb[(size_t)row * 9216 + qn];
                qnext[2*i+1] = qkb[(size_t)(row + 1) * 9216 + qn];
            }
        }
        // qv copy LDG (64 channels per chunk), STG after MMAs
        float4 qvr[4];
        #pragma unroll
        for (int k = 0; k < 4; k++) {
            int idx = tid + k * 512;
            int r = idx >> 5, col = idx & 31;
            qvr[k] = ((const float4*)(qvb + (size_t)(cc * 64 + r) * 9216))[col];
        }
        if (cc < 7) cp_wait1(); else cp_wait0();
        __syncthreads();
        // MMAs on buffers [cur]
        #pragma unroll
        for (int kf = 0; kf < 2; kf++) {
            int kb0 = kf * 16;
            unsigned bh[2], bl[2];
            ldsm2(bh, qkbuf + ((w * 8 + lane7) * 40 + kb0 + laneb * 8) * 2);
            ldsm2(bl, qkbuf + 10240 + ((w * 8 + lane7) * 40 + kb0 + laneb * 8) * 2);
            #pragma unroll
            for (int mf = 0; mf < 9; mf++) {
                unsigned ah[4], al[4];
                ldsm4(ah, mkb + ((mf * 16 + lane15) * 40 + kb0 + lanehalf * 8) * 2);
                ldsm4(al, mkb + 11520 + ((mf * 16 + lane15) * 40 + kb0 + lanehalf * 8) * 2);
                mma_bf16(acc[mf], ah, bh);
                mma_bf16(acc[mf], ah, bl);
                mma_bf16(acc[mf], al, bh);
            }
        }
        __syncthreads();
        // qv STG
        #pragma unroll
        for (int k = 0; k < 4; k++) {
            int idx = tid + k * 512;
            int r = idx >> 5, col = idx & 31;
            ((float4*)(outb + (size_t)(cc * 64 + r) * 9216))[col] = qvr[k];
        }
        #pragma unroll
        for (int i = 0; i < 8; i++) qcur[i] = qnext[i];
    }

    // ---------------- prologue AV stage 0 (overlaps softmax) ----------------
    {
        #pragma unroll
        for (int it = 0; it < 2; it++) {
            int idx = tid + it * 512;
            int hl = idx & 1, part = (idx >> 1) & 1, r = idx >> 2;
            const __nv_bfloat16* src = (hl ? g_mvl : g_mvh)
                                     + ((size_t)(b * 512 + r)) * 144 + part * 8;
            cp16(sbase + 77824 + hl * 12288 + (r * 24 + part * 8) * 2, src);
        }
        cp_commit();
    }

    // ---------------- softmax over m (cols n = w*8 + 2tq + {0,1}) ----------------
    {
        float mx0 = -1e30f, mx1 = -1e30f;
        #pragma unroll
        for (int mf = 0; mf < 9; mf++) {
            mx0 = fmaxf(mx0, fmaxf(acc[mf][0], acc[mf][2]));
            mx1 = fmaxf(mx1, fmaxf(acc[mf][1], acc[mf][3]));
        }
        #pragma unroll
        for (int off = 4; off <= 16; off <<= 1) {
            mx0 = fmaxf(mx0, __shfl_xor_sync(0xffffffffu, mx0, off));
            mx1 = fmaxf(mx1, __shfl_xor_sync(0xffffffffu, mx1, off));
        }
        float s0 = 0.f, s1 = 0.f;
        #pragma unroll
        for (int mf = 0; mf < 9; mf++) {
            acc[mf][0] = __expf(acc[mf][0] - mx0);
            acc[mf][1] = __expf(acc[mf][1] - mx1);
            acc[mf][2] = __expf(acc[mf][2] - mx0);
            acc[mf][3] = __expf(acc[mf][3] - mx1);
            s0 += acc[mf][0] + acc[mf][2];
            s1 += acc[mf][1] + acc[mf][3];
        }
        #pragma unroll
        for (int off = 4; off <= 16; off <<= 1) {
            s0 += __shfl_xor_sync(0xffffffffu, s0, off);
            s1 += __shfl_xor_sync(0xffffffffu, s1, off);
        }
        float in0 = 1.0f / s0, in1 = 1.0f / s1;
        int ncol0 = w * 8 + 2 * tq, ncol1 = ncol0 + 1;
        #pragma unroll
        for (int mf = 0; mf < 9; mf++) {
            int m0 = mf * 16 + g, m1 = m0 + 8;
            __nv_bfloat16 hi, lo;
            split_bf16(acc[mf][0] * in0, hi, lo);
            attT_hi[ncol0 * 152 + m0] = hi; attT_lo[ncol0 * 152 + m0] = lo;
            split_bf16(acc[mf][1] * in1, hi, lo);
            attT_hi[ncol1 * 152 + m0] = hi; attT_lo[ncol1 * 152 + m0] = lo;
            split_bf16(acc[mf][2] * in0, hi, lo);
            attT_hi[ncol0 * 152 + m1] = hi; attT_lo[ncol0 * 152 + m1] = lo;
            split_bf16(acc[mf][3] * in1, hi, lo);
            attT_hi[ncol1 * 152 + m1] = hi; attT_lo[ncol1 * 152 + m1] = lo;
        }
    }

    // ---------------- phase 2: AV, flat pipeline over 18 stages ----------------
    // warp: nf = w>>1 (n-frag of 16 rows), vq = w&1 (128-v subrange); acc2[16 j][4]
    int nf = w >> 1, vq = w & 1;
    float acc2[16][4];
    for (int s = 0; s < 18; s++) {
        int p = s / 9, kf = s % 9;
        // stage s+1
        if (s < 17) {
            int p1 = (s + 1) / 9, kf1 = (s + 1) % 9;
            uint32_t mvb = sbase + 77824 + ((s + 1) & 1) * 24576;
            #pragma unroll
            for (int it = 0; it < 2; it++) {
                int idx = tid + it * 512;
                int hl = idx & 1, part = (idx >> 1) & 1, r = idx >> 2;
                const __nv_bfloat16* src = (hl ? g_mvl : g_mvh)
                    + ((size_t)(b * 512 + p1 * 256 + r)) * 144 + kf1 * 16 + part * 8;
                cp16(mvb + hl * 12288 + (r * 24 + part * 8) * 2, src);
            }
            cp_commit();
        }
        if (s < 17) cp_wait1(); else cp_wait0();
        __syncthreads();
        if (kf == 0) {
            #pragma unroll
            for (int j = 0; j < 16; j++)
                #pragma unroll
                for (int q = 0; q < 4; q++) acc2[j][q] = 0.f;
        }
        // compute on buf[s&1]
        {
            uint32_t mvb = sbase + 77824 + (s & 1) * 24576;
            int kb0 = kf * 16;
            unsigned ah[4], al[4];
            ldsm4(ah, sbase + ((nf * 16 + lane15) * 152 + kb0 + lanehalf * 8) * 2);
            ldsm4(al, sbase + 38912 + ((nf * 16 + lane15) * 152 + kb0 + lanehalf * 8) * 2);
            #pragma unroll 4
            for (int j = 0; j < 16; j++) {
                int r = vq * 128 + j * 8 + lane7;
                unsigned bh[2], bl[2];
                ldsm2(bh, mvb + (r * 24 + laneb * 8) * 2);
                ldsm2(bl, mvb + 12288 + (r * 24 + laneb * 8) * 2);
                mma_bf16(acc2[j], ah, bh);
                mma_bf16(acc2[j], ah, bl);
                mma_bf16(acc2[j], al, bh);
            }
        }
        __syncthreads();
        // epilogue at end of each p-pass
        if (kf == 8) {
            #pragma unroll
            for (int j = 0; j < 16; j++) {
                int v = p * 256 + vq * 128 + j * 8 + 2 * tq;
                float* p0 = outb + (size_t)(512 + v) * 9216 + 16 * nf + g;
                p0[0]        = acc2[j][0];
                p0[8]        = acc2[j][2];
                p0[9216]     = acc2[j][1];
                p0[9216 + 8] = acc2[j][3];
            }
        }
    }
}

// ================= launch =================
extern "C" void kernel_launch(void* const* d_in, const int* in_sizes, int n_in,
                              void* d_out, int out_size) {
    const float* mk = (const float*)d_in[0];
    const float* mv = (const float*)d_in[1];
    const float* qk = (const float*)d_in[2];
    const float* qv = (const float*)d_in[3];
    const float* kw = (const float*)d_in[4];
    const float* kb = (const float*)d_in[5];
    const float* vw = (const float*)d_in[6];
    const float* vb = (const float*)d_in[7];
    float* out = (float*)d_out;

    // 2048 key planes + 4096 value planes (T*B*Cv) — R10-12 regression was 4096 total
    k_pool<<<6144, 256>>>(mk, mv);
    k_conv<<<800, 256>>>(kw, kb, vw, vb);
    k_upsample<<<864, 256>>>();
    cudaFuncSetAttribute(k_attn, cudaFuncAttributeMaxDynamicSharedMemorySize, 126976);
    k_attn<<<144, 512, 126976>>>(qk, qv, out);
}

// round 14
// speedup vs baseline: 1.2574x; 1.2574x over previous
#include <cuda_runtime.h>
#include <cuda_bf16.h>
#include <cstdint>

// ---------------- problem constants ----------------
// T=4, B=2, Ck=256, Cv=512, H=W=96, scales {1,2,3,6}, MAX=6, M=144, N=9216

// ---------------- device scratch (static, no allocation) ----------------
__device__ __align__(16) float g_pool6_k[2048 * 36];
__device__ __align__(16) float g_pool6_v[4096 * 36];
__device__ __align__(16) float g_convk[4 * 2 * 4 * 64 * 36];
__device__ __align__(16) float g_convv[4 * 2 * 4 * 128 * 36];
__device__ __align__(16) __nv_bfloat16 g_mkh[2 * 144 * 256];  // [b][m][c] hi (x Ck^-0.5)
__device__ __align__(16) __nv_bfloat16 g_mkl[2 * 144 * 256];  // lo
__device__ __align__(16) __nv_bfloat16 g_mvh[2 * 512 * 144];  // [b][v][m] hi
__device__ __align__(16) __nv_bfloat16 g_mvl[2 * 512 * 144];  // lo

__constant__ int c_scale[4] = {1, 2, 3, 6};
__constant__ int UI0[4][6] = {
    {0,0,0,0,0,0},
    {0,0,0,0,1,1},
    {0,0,0,1,1,2},
    {0,1,2,3,4,5}};
__constant__ int UI1[4][6] = {
    {0,0,0,0,0,0},
    {0,1,1,1,1,1},
    {0,1,1,2,2,2},
    {0,1,2,3,4,5}};
__constant__ float UW[4][6] = {
    {0.f,0.f,0.f,0.f,0.f,0.f},
    {0.f, 1.f/6.f, 0.5f, 5.f/6.f, 0.f, 0.f},
    {0.f, 0.25f, 0.75f, 0.25f, 0.75f, 0.f},
    {0.f,0.f,0.f,0.f,0.f,0.f}};

// ---------------- helpers ----------------
__device__ __forceinline__ void mma_bf16(float* d, const unsigned* a, const unsigned* b) {
    asm volatile(
        "mma.sync.aligned.m16n8k16.row.col.f32.bf16.bf16.f32 "
        "{%0,%1,%2,%3}, {%4,%5,%6,%7}, {%8,%9}, {%0,%1,%2,%3};"
        : "+f"(d[0]), "+f"(d[1]), "+f"(d[2]), "+f"(d[3])
        : "r"(a[0]), "r"(a[1]), "r"(a[2]), "r"(a[3]), "r"(b[0]), "r"(b[1]));
}
__device__ __forceinline__ void split_bf16(float x, __nv_bfloat16& hi, __nv_bfloat16& lo) {
    hi = __float2bfloat16(x);
    lo = __float2bfloat16(x - __bfloat162float(hi));
}
__device__ __forceinline__ unsigned packbf(__nv_bfloat16 l, __nv_bfloat16 h) {
    return ((unsigned)__bfloat16_as_ushort(h) << 16) | (unsigned)__bfloat16_as_ushort(l);
}

// ================= K1: 16x16 block means + qv passthrough copy =================
__global__ void k_pool(const float* __restrict__ mk, const float* __restrict__ mv,
                       const float* __restrict__ qv, float* __restrict__ out) {
    int p = blockIdx.x;
    int tid = threadIdx.x;
    if (p >= 6144) {
        // qv copy: out[b][0..511][n] = qv[b][ch][n]; 2304 blocks x 4096 floats
        int p2 = p - 6144;
        const float4* src = (const float4*)qv;
        float4* dst = (float4*)out;
        #pragma unroll
        for (int k = 0; k < 4; k++) {
            size_t f4 = (size_t)p2 * 1024 + tid + k * 256;
            size_t b = f4 / (512 * 2304);
            dst[f4 + b * 512 * 2304] = src[f4];
        }
        return;
    }
    const float* src; float* dst;
    if (p < 2048) { src = mk + (size_t)p * 9216; dst = g_pool6_k + (size_t)p * 36; }
    else { int q = p - 2048; src = mv + (size_t)q * 9216; dst = g_pool6_v + (size_t)q * 36; }
    __shared__ float rowsum[576];
    for (int task = tid; task < 576; task += 256) {
        int r = task / 6, j = task % 6;
        const float4* a = (const float4*)(src + r * 96 + j * 16);
        float4 v0 = a[0], v1 = a[1], v2 = a[2], v3 = a[3];
        rowsum[task] = (v0.x+v0.y+v0.z+v0.w) + (v1.x+v1.y+v1.z+v1.w)
                     + (v2.x+v2.y+v2.z+v2.w) + (v3.x+v3.y+v3.z+v3.w);
    }
    __syncthreads();
    if (tid < 36) {
        int by = tid / 6, bx = tid % 6;
        float s = 0.f;
        #pragma unroll
        for (int k = 0; k < 16; k++) s += rowsum[(by * 16 + k) * 6 + bx];
        dst[tid] = s * (1.0f / 256.0f);
    }
}

// ================= K2: per-(t,b,scale,pos) 1x1 conv + bias + relu =================
__global__ void k_conv(const float* __restrict__ kw, const float* __restrict__ kb,
                       const float* __restrict__ vw, const float* __restrict__ vb) {
    __shared__ float pooled[512];
    int bi = blockIdx.x;
    int kv = bi / 400;
    int rem = bi % 400;
    int tb = rem / 50;
    int task = rem % 50;
    int si, pos;
    if (task < 1)       { si = 0; pos = 0; }
    else if (task < 5)  { si = 1; pos = task - 1; }
    else if (task < 14) { si = 2; pos = task - 5; }
    else                { si = 3; pos = task - 14; }
    int s = c_scale[si];
    int g = 6 / s;
    int pi = pos / s, pj = pos % s;
    int C  = kv ? 512 : 256;
    int Co = kv ? 128 : 64;
    const float* p6 = kv ? g_pool6_v : g_pool6_k;
    int tid = threadIdx.x;
    float ginv = 1.0f / (float)(g * g);
    for (int c = tid; c < C; c += 256) {
        const float* pp = p6 + (size_t)(tb * C + c) * 36;
        float sum = 0.f;
        for (int a = 0; a < g; a++)
            for (int bb = 0; bb < g; bb++)
                sum += pp[(pi * g + a) * 6 + (pj * g + bb)];
        pooled[c] = sum * ginv;
    }
    __syncthreads();
    int t = tb >> 1;
    int L = 256 / Co;
    int o = tid / L, r = tid % L;
    int chunk = C / L;
    const float* w = (kv ? vw : kw) + (size_t)((t * 4 + si) * Co + o) * C + r * chunk;
    const float* pl = pooled + r * chunk;
    float partial = 0.f;
    for (int i = 0; i < chunk; i += 4) {
        float4 wv = *(const float4*)(w + i);
        float4 pv = *(const float4*)(pl + i);
        partial += wv.x * pv.x + wv.y * pv.y + wv.z * pv.z + wv.w * pv.w;
    }
    for (int off = 1; off < L; off <<= 1)
        partial += __shfl_xor_sync(0xffffffffu, partial, off);
    if (r == 0) {
        float bias = (kv ? vb : kb)[(t * 4 + si) * Co + o];
        float v = fmaxf(partial + bias, 0.0f);
        float* cdst = (kv ? g_convv : g_convk) + (size_t)((tb * 4 + si) * Co + o) * 36 + pos;
        *cdst = v;
    }
}

// ================= K3: bilinear upsample + bf16 hi/lo layouts =================
__global__ void k_upsample() {
    int idx = blockIdx.x * 256 + threadIdx.x;
    if (idx >= 221184) return;
    if (idx < 73728) {
        int b = idx / (256 * 144);
        int rr = idx % (256 * 144);
        int c = rr / 144, m = rr % 144;
        int t = m / 36, pp = m % 36, i6 = pp / 6, j6 = pp % 6;
        int si = c >> 6, o = c & 63;
        int s = c_scale[si];
        const float* cv = g_convk + (size_t)(((t * 2 + b) * 4 + si) * 64 + o) * 36;
        int yi0 = UI0[si][i6], yi1 = UI1[si][i6]; float wy = UW[si][i6];
        int xi0 = UI0[si][j6], xi1 = UI1[si][j6]; float wx = UW[si][j6];
        float v00 = cv[yi0 * s + xi0], v01 = cv[yi0 * s + xi1];
        float v10 = cv[yi1 * s + xi0], v11 = cv[yi1 * s + xi1];
        float v = (1.f - wy) * ((1.f - wx) * v00 + wx * v01)
                +        wy  * ((1.f - wx) * v10 + wx * v11);
        v *= 0.0625f;
        __nv_bfloat16 hi, lo;
        split_bf16(v, hi, lo);
        size_t di = (size_t)(b * 144 + m) * 256 + c;
        g_mkh[di] = hi; g_mkl[di] = lo;
    } else {
        int r0 = idx - 73728;
        int b = r0 / (144 * 512);
        int rr = r0 % (144 * 512);
        int m = rr / 512, vch = rr % 512;
        int t = m / 36, pp = m % 36, i6 = pp / 6, j6 = pp % 6;
        int si = vch >> 7, o = vch & 127;
        int s = c_scale[si];
        const float* cv = g_convv + (size_t)(((t * 2 + b) * 4 + si) * 128 + o) * 36;
        int yi0 = UI0[si][i6], yi1 = UI1[si][i6]; float wy = UW[si][i6];
        int xi0 = UI0[si][j6], xi1 = UI1[si][j6]; float wx = UW[si][j6];
        float v00 = cv[yi0 * s + xi0], v01 = cv[yi0 * s + xi1];
        float v10 = cv[yi1 * s + xi0], v11 = cv[yi1 * s + xi1];
        float v = (1.f - wy) * ((1.f - wx) * v00 + wx * v01)
                +        wy  * ((1.f - wx) * v10 + wx * v11);
        __nv_bfloat16 hi, lo;
        split_bf16(v, hi, lo);
        size_t di = (size_t)(b * 512 + vch) * 144 + m;
        g_mvh[di] = hi; g_mvl[di] = lo;
    }
}

// ================= K4: tensor-core attention, register-buffered staging =================
// grid 144 = 2 b * 72 n-tiles of 128; 512 threads = 16 warps. Scalar frag loads (R9-proven).
//
// smem byte layout:
//   QK phase : mkch_hi @0      [144m][40c]  11520
//              mkch_lo @11520               11520
//              qkT_hi  @23040  [128n][40c]  10240
//              qkT_lo  @33280               10240   (ends 43520)
//   AV phase : attT_hi @0      [128n][152m] 38912
//              attT_lo @38912               38912   (ends 77824)
//              mvch_hi @77824  [128r][56k]  14336   (48 valid k per stage, pitch 56)
//              mvch_lo @92160               14336   total 106496
__global__ __launch_bounds__(512, 1)
void k_attn(const float* __restrict__ qk, float* __restrict__ out) {
    extern __shared__ char smem[];
    __nv_bfloat16* attT_hi = (__nv_bfloat16*)(smem);
    __nv_bfloat16* attT_lo = (__nv_bfloat16*)(smem + 38912);
    __nv_bfloat16* mvch_hi = (__nv_bfloat16*)(smem + 77824);
    __nv_bfloat16* mvch_lo = (__nv_bfloat16*)(smem + 92160);
    __nv_bfloat16* mkch_hi = (__nv_bfloat16*)(smem);
    __nv_bfloat16* mkch_lo = (__nv_bfloat16*)(smem + 11520);
    __nv_bfloat16* qkT_hi  = (__nv_bfloat16*)(smem + 23040);
    __nv_bfloat16* qkT_lo  = (__nv_bfloat16*)(smem + 33280);

    int tid = threadIdx.x;
    int w = tid >> 5, lane = tid & 31;
    int g = lane >> 2, tq = lane & 3;
    int b = blockIdx.x / 72, ntile = blockIdx.x % 72;
    int n0 = ntile * 128;

    const float* qkb = qk + (size_t)b * 256 * 9216 + n0;

    // ---------------- phase 1: QK scores ----------------
    float acc[9][4];
    #pragma unroll
    for (int i = 0; i < 9; i++)
        #pragma unroll
        for (int j = 0; j < 4; j++) acc[i][j] = 0.f;

    // qk register prefetch: thread owns column qn, even c-base cb (rows cb+8i, cb+8i+1)
    int qn = tid & 127;
    int cb = (tid >> 7) * 2;
    float qcur[8], qnext[8];
    uint4 mkreg[3];

    // prologue: LDG mk(0) + qk(0) into regs, then STS
    #pragma unroll
    for (int i = 0; i < 3; i++) {
        int q = tid + i * 512;
        if (q < 1152) {
            int hl = q / 576, rem = q % 576;
            int m = rem % 144, part = rem / 144;
            mkreg[i] = *(const uint4*)((hl ? g_mkl : g_mkh)
                       + ((size_t)(b * 144 + m)) * 256 + part * 8);
        }
    }
    #pragma unroll
    for (int i = 0; i < 4; i++) {
        int row = cb + i * 8;
        qcur[2*i]   = qkb[(size_t)row * 9216 + qn];
        qcur[2*i+1] = qkb[(size_t)(row + 1) * 9216 + qn];
    }
    #pragma unroll
    for (int i = 0; i < 3; i++) {
        int q = tid + i * 512;
        if (q < 1152) {
            int hl = q / 576, rem = q % 576;
            int m = rem % 144, part = rem / 144;
            *(uint4*)((hl ? mkch_lo : mkch_hi) + m * 40 + part * 8) = mkreg[i];
        }
    }
    #pragma unroll
    for (int i = 0; i < 4; i++) {
        int c0 = cb + i * 8;
        __nv_bfloat16 h0, l0, h1, l1;
        split_bf16(qcur[2*i], h0, l0);
        split_bf16(qcur[2*i+1], h1, l1);
        *(unsigned*)(qkT_hi + qn * 40 + c0) = packbf(h0, h1);
        *(unsigned*)(qkT_lo + qn * 40 + c0) = packbf(l0, l1);
    }
    __syncthreads();

    for (int cc = 0; cc < 8; cc++) {
        // LDG next chunk into regs (hidden behind MMAs)
        if (cc < 7) {
            #pragma unroll
            for (int i = 0; i < 3; i++) {
                int q = tid + i * 512;
                if (q < 1152) {
                    int hl = q / 576, rem = q % 576;
                    int m = rem % 144, part = rem / 144;
                    mkreg[i] = *(const uint4*)((hl ? g_mkl : g_mkh)
                               + ((size_t)(b * 144 + m)) * 256 + (cc + 1) * 32 + part * 8);
                }
            }
            #pragma unroll
            for (int i = 0; i < 4; i++) {
                int row = (cc + 1) * 32 + cb + i * 8;
                qnext[2*i]   = qkb[(size_t)row * 9216 + qn];
                qnext[2*i+1] = qkb[(size_t)(row + 1) * 9216 + qn];
            }
        }
        // MMAs on current buffer (R9 scalar addressing)
        #pragma unroll
        for (int kf = 0; kf < 2; kf++) {
            int kb0 = kf * 16 + 2 * tq;
            unsigned bh[2], bl[2];
            const __nv_bfloat16* brow = qkT_hi + (w * 8 + g) * 40 + kb0;
            bh[0] = *(const unsigned*)(brow);
            bh[1] = *(const unsigned*)(brow + 8);
            const __nv_bfloat16* brol = qkT_lo + (w * 8 + g) * 40 + kb0;
            bl[0] = *(const unsigned*)(brol);
            bl[1] = *(const unsigned*)(brol + 8);
            #pragma unroll
            for (int mf = 0; mf < 9; mf++) {
                const __nv_bfloat16* ah0 = mkch_hi + (mf * 16 + g) * 40 + kb0;
                const __nv_bfloat16* al0 = mkch_lo + (mf * 16 + g) * 40 + kb0;
                unsigned ah[4], al[4];
                ah[0] = *(const unsigned*)(ah0);
                ah[1] = *(const unsigned*)(ah0 + 8 * 40);
                ah[2] = *(const unsigned*)(ah0 + 8);
                ah[3] = *(const unsigned*)(ah0 + 8 * 40 + 8);
                al[0] = *(const unsigned*)(al0);
                al[1] = *(const unsigned*)(al0 + 8 * 40);
                al[2] = *(const unsigned*)(al0 + 8);
                al[3] = *(const unsigned*)(al0 + 8 * 40 + 8);
                mma_bf16(acc[mf], ah, bh);
                mma_bf16(acc[mf], ah, bl);
                mma_bf16(acc[mf], al, bh);
            }
        }
        __syncthreads();
        // STS next chunk
        if (cc < 7) {
            #pragma unroll
            for (int i = 0; i < 3; i++) {
                int q = tid + i * 512;
                if (q < 1152) {
                    int hl = q / 576, rem = q % 576;
                    int m = rem % 144, part = rem / 144;
                    *(uint4*)((hl ? mkch_lo : mkch_hi) + m * 40 + part * 8) = mkreg[i];
                }
            }
            #pragma unroll
            for (int i = 0; i < 4; i++) {
                int c0 = cb + i * 8;
                __nv_bfloat16 h0, l0, h1, l1;
                split_bf16(qnext[2*i], h0, l0);
                split_bf16(qnext[2*i+1], h1, l1);
                *(unsigned*)(qkT_hi + qn * 40 + c0) = packbf(h0, h1);
                *(unsigned*)(qkT_lo + qn * 40 + c0) = packbf(l0, l1);
            }
            __syncthreads();
        }
    }
    // last QK MMA done; barrier above (cc==7 falls through without STS) — need one
    __syncthreads();   // protect attT region (overlaps qkT) -- all QK reads complete

    // ---------------- AV stage-0 LDG (overlaps softmax) ----------------
    // stage s: p = s/3, ks = (s%3)*48; rows r 0..127 -> v = (r>>6)*256 + p*64 + (r&63)
    uint4 mvreg[3];
    {
        #pragma unroll
        for (int it = 0; it < 3; it++) {
            int idx = tid + it * 512;          // 1536 uint4 per stage
            int hl = idx / 768, rem = idx % 768;
            int r = rem / 6, part = rem % 6;
            int v = ((r >> 6) << 8) + (r & 63);   // p=0, ks=0
            mvreg[it] = *(const uint4*)((hl ? g_mvl : g_mvh)
                        + ((size_t)(b * 512 + v)) * 144 + part * 8);
        }
    }

    // ---------------- softmax over m (cols n = w*8 + 2tq + {0,1}) ----------------
    {
        float mx0 = -1e30f, mx1 = -1e30f;
        #pragma unroll
        for (int mf = 0; mf < 9; mf++) {
            mx0 = fmaxf(mx0, fmaxf(acc[mf][0], acc[mf][2]));
            mx1 = fmaxf(mx1, fmaxf(acc[mf][1], acc[mf][3]));
        }
        #pragma unroll
        for (int off = 4; off <= 16; off <<= 1) {
            mx0 = fmaxf(mx0, __shfl_xor_sync(0xffffffffu, mx0, off));
            mx1 = fmaxf(mx1, __shfl_xor_sync(0xffffffffu, mx1, off));
        }
        float s0 = 0.f, s1 = 0.f;
        #pragma unroll
        for (int mf = 0; mf < 9; mf++) {
            acc[mf][0] = __expf(acc[mf][0] - mx0);
            acc[mf][1] = __expf(acc[mf][1] - mx1);
            acc[mf][2] = __expf(acc[mf][2] - mx0);
            acc[mf][3] = __expf(acc[mf][3] - mx1);
            s0 += acc[mf][0] + acc[mf][2];
            s1 += acc[mf][1] + acc[mf][3];
        }
        #pragma unroll
        for (int off = 4; off <= 16; off <<= 1) {
            s0 += __shfl_xor_sync(0xffffffffu, s0, off);
            s1 += __shfl_xor_sync(0xffffffffu, s1, off);
        }
        float in0 = 1.0f / s0, in1 = 1.0f / s1;
        int ncol0 = w * 8 + 2 * tq, ncol1 = ncol0 + 1;
        #pragma unroll
        for (int mf = 0; mf < 9; mf++) {
            int m0 = mf * 16 + g, m1 = m0 + 8;
            __nv_bfloat16 hi, lo;
            split_bf16(acc[mf][0] * in0, hi, lo);
            attT_hi[ncol0 * 152 + m0] = hi; attT_lo[ncol0 * 152 + m0] = lo;
            split_bf16(acc[mf][1] * in1, hi, lo);
            attT_hi[ncol1 * 152 + m0] = hi; attT_lo[ncol1 * 152 + m0] = lo;
            split_bf16(acc[mf][2] * in0, hi, lo);
            attT_hi[ncol0 * 152 + m1] = hi; attT_lo[ncol0 * 152 + m1] = lo;
            split_bf16(acc[mf][3] * in1, hi, lo);
            attT_hi[ncol1 * 152 + m1] = hi; attT_lo[ncol1 * 152 + m1] = lo;
        }
    }

    // STS stage 0
    #pragma unroll
    for (int it = 0; it < 3; it++) {
        int idx = tid + it * 512;
        int hl = idx / 768, rem = idx % 768;
        int r = rem / 6, part = rem % 6;
        *(uint4*)((hl ? mvch_lo : mvch_hi) + r * 56 + part * 8) = mvreg[it];
    }
    __syncthreads();   // attT + mvch stage0 visible

    // ---------------- phase 2: AV, 12 stages of 48k (4 p-passes x 3) ----------------
    int mfa = w & 7;       // output n-frag (8 frags of 16 rows)
    int vhalf = w >> 3;    // which 64-row half of the staged 128 rows
    float acc2[8][4];
    for (int s = 0; s < 12; s++) {
        int p = s / 3, kq = s % 3, ks = kq * 48;
        if (kq == 0) {
            #pragma unroll
            for (int j = 0; j < 8; j++)
                #pragma unroll
                for (int q = 0; q < 4; q++) acc2[j][q] = 0.f;
        }
        // LDG next stage into regs (hidden behind MMAs)
        if (s < 11) {
            int p1 = (s + 1) / 3, ks1 = ((s + 1) % 3) * 48;
            #pragma unroll
            for (int it = 0; it < 3; it++) {
                int idx = tid + it * 512;
                int hl = idx / 768, rem = idx % 768;
                int r = rem / 6, part = rem % 6;
                int v = ((r >> 6) << 8) + p1 * 64 + (r & 63);
                mvreg[it] = *(const uint4*)((hl ? g_mvl : g_mvh)
                            + ((size_t)(b * 512 + v)) * 144 + ks1 + part * 8);
            }
        }
        // MMAs on current stage: 3 k-frags of 16
        #pragma unroll
        for (int kfi = 0; kfi < 3; kfi++) {
            int kb0 = ks + kfi * 16 + 2 * tq;          // absolute k for attT
            int kl0 = kfi * 16 + 2 * tq;               // stage-local k for mvch
            const __nv_bfloat16* ah0 = attT_hi + (mfa * 16 + g) * 152 + kb0;
            const __nv_bfloat16* al0 = attT_lo + (mfa * 16 + g) * 152 + kb0;
            unsigned ah[4], al[4];
            ah[0] = *(const unsigned*)(ah0);
            ah[1] = *(const unsigned*)(ah0 + 8 * 152);
            ah[2] = *(const unsigned*)(ah0 + 8);
            ah[3] = *(const unsigned*)(ah0 + 8 * 152 + 8);
            al[0] = *(const unsigned*)(al0);
            al[1] = *(const unsigned*)(al0 + 8 * 152);
            al[2] = *(const unsigned*)(al0 + 8);
            al[3] = *(const unsigned*)(al0 + 8 * 152 + 8);
            #pragma unroll
            for (int j = 0; j < 8; j++) {
                int r = vhalf * 64 + j * 8 + g;
                unsigned bh[2], bl[2];
                const __nv_bfloat16* brow = mvch_hi + r * 56 + kl0;
                bh[0] = *(const unsigned*)(brow);
                bh[1] = *(const unsigned*)(brow + 8);
                const __nv_bfloat16* brol = mvch_lo + r * 56 + kl0;
                bl[0] = *(const unsigned*)(brol);
                bl[1] = *(const unsigned*)(brol + 8);
                mma_bf16(acc2[j], ah, bh);
                mma_bf16(acc2[j], ah, bl);
                mma_bf16(acc2[j], al, bh);
            }
        }
        __syncthreads();   // all warps done reading current stage
        // epilogue at end of each p-pass
        if (kq == 2) {
            #pragma unroll
            for (int j = 0; j < 8; j++) {
                int v = vhalf * 256 + p * 64 + j * 8 + 2 * tq;
                float* p0 = out + (size_t)(b * 1024 + 512 + v) * 9216 + n0 + 16 * mfa + g;
                p0[0]        = acc2[j][0];
                p0[8]        = acc2[j][2];
                p0[9216]     = acc2[j][1];
                p0[9216 + 8] = acc2[j][3];
            }
        }
        // STS next stage
        if (s < 11) {
            #pragma unroll
            for (int it = 0; it < 3; it++) {
                int idx = tid + it * 512;
                int hl = idx / 768, rem = idx % 768;
                int r = rem / 6, part = rem % 6;
                *(uint4*)((hl ? mvch_lo : mvch_hi) + r * 56 + part * 8) = mvreg[it];
            }
            __syncthreads();
        }
    }
}

// ================= launch =================
extern "C" void kernel_launch(void* const* d_in, const int* in_sizes, int n_in,
                              void* d_out, int out_size) {
    const float* mk = (const float*)d_in[0];
    const float* mv = (const float*)d_in[1];
    const float* qk = (const float*)d_in[2];
    const float* qv = (const float*)d_in[3];
    const float* kw = (const float*)d_in[4];
    const float* kb = (const float*)d_in[5];
    const float* vw = (const float*)d_in[6];
    const float* vb = (const float*)d_in[7];
    float* out = (float*)d_out;

    // 2048 key planes + 4096 value planes + 2304 qv-copy blocks
    k_pool<<<8448, 256>>>(mk, mv, qv, out);
    k_conv<<<800, 256>>>(kw, kb, vw, vb);
    k_upsample<<<864, 256>>>();
    cudaFuncSetAttribute(k_attn, cudaFuncAttributeMaxDynamicSharedMemorySize, 106496);
    k_attn<<<144, 512, 106496>>>(qk, out);
}